// round 16
// baseline (speedup 1.0000x reference)
#include <cuda_runtime.h>
#include <cuda_bf16.h>

// ---------------- problem constants ----------------
#define BB     16
#define CCH    256
#define HH     56
#define WWID   56
#define NN     3136          // 56*56
#define NHEADS 4
#define DK     16
#define DU     4
#define DVV    64
#define RR     15
// conv pad = 7

typedef unsigned long long ull;

// ---------------- scratch (device globals; no allocations allowed) ----------------
__device__ float g_q[BB * 64 * NN];    // [b][h*16+k][n]   (BN applied)
__device__ float g_k[BB * 64 * NN];    // [b][u*16+k][n]   (raw logits; softmax fused into lc)
__device__ float g_v2[BB * NN * 256];  // [b][n][u*64+v]   (n-major, BN applied)
__device__ float g_Lc[BB * DK * DVV];  // [b][k][v]
__device__ float g_m[BB * 64];         // per-row softmax max
__device__ float g_is[BB * 64];        // per-row 1/sum

// ---------------- f32x2 helpers (sm_103a packed fp32 pipe) ----------------
__device__ __forceinline__ void ffma2(ull &d, ull a, ull b) {
    asm volatile("fma.rn.f32x2 %0, %1, %2, %0;" : "+l"(d) : "l"(a), "l"(b));
}
__device__ __forceinline__ ull pack2(float x) {
    ull r; asm("mov.b64 %0, {%1, %1};" : "=l"(r) : "f"(x)); return r;
}
__device__ __forceinline__ ull fpack(float lo, float hi) {
    ull r; asm("mov.b64 %0, {%1, %2};" : "=l"(r) : "f"(lo), "f"(hi)); return r;
}
__device__ __forceinline__ void funpack(ull v, float &lo, float &hi) {
    asm("mov.b64 {%0, %1}, %2;" : "=f"(lo), "=f"(hi) : "l"(v));
}

// ---------------- kernel 0: projections + BN; v written n-major; zeroes Lc ------
// R16: weights staged as pre-duplicated f32x2 pairs (Wsd) -> inner loop reads
// 2 broadcast LDS.128 per ccl instead of 4 scalar LDS.32 + dup-MOVs.
__global__ void __launch_bounds__(256) proj_kernel(
    const float* __restrict__ x,
    const float* __restrict__ Wq, const float* __restrict__ Wk, const float* __restrict__ Wv,
    const float* __restrict__ gq, const float* __restrict__ bq,
    const float* __restrict__ mq, const float* __restrict__ vq,
    const float* __restrict__ gv, const float* __restrict__ bv,
    const float* __restrict__ mv, const float* __restrict__ vv)
{
    __shared__ float xs[32 * 128];
    __shared__ ull  Wsd[32 * 64];

    const int b  = blockIdx.z;
    const int db = blockIdx.y;
    const int n0 = blockIdx.x * 128;
    const int t  = threadIdx.x;
    const int tx = t & 15;
    const int ty = t >> 4;

    // fold zero_lc in (g_Lc only written later by lc_kernel)
    if (db == 0 && blockIdx.x == 0)
        for (int s = t; s < 1024; s += 256) g_Lc[(size_t)b * 1024 + s] = 0.f;

    const float* Wsrc; int dstride, dcol0;
    if (db == 0)      { Wsrc = Wq; dstride = 64;  dcol0 = 0; }
    else if (db == 1) { Wsrc = Wk; dstride = 64;  dcol0 = 0; }
    else              { Wsrc = Wv; dstride = 256; dcol0 = (db - 2) * 64; }

    ull acc[16];
#pragma unroll
    for (int i = 0; i < 16; i++) acc[i] = 0ull;

    for (int c0 = 0; c0 < CCH; c0 += 32) {
        __syncthreads();
        for (int s = t; s < 32 * 128; s += 256) {
            int cc = s >> 7, nn = s & 127;
            int g = n0 + nn;
            xs[s] = (g < NN) ? x[(size_t)(b * CCH + c0 + cc) * NN + g] : 0.f;
        }
        for (int s = t; s < 32 * 64; s += 256) {
            int cc = s >> 6, dd = s & 63;
            Wsd[s] = pack2(Wsrc[(size_t)(c0 + cc) * dstride + dcol0 + dd]);
        }
        __syncthreads();

#pragma unroll 8
        for (int ccl = 0; ccl < 32; ccl++) {
            ull xv[4];
#pragma unroll
            for (int j = 0; j < 4; j++)
                xv[j] = *(const ull*)&xs[ccl * 128 + ((tx + 16 * j) << 1)];
            const ulonglong2* wp = (const ulonglong2*)&Wsd[ccl * 64 + ty * 4];
            ulonglong2 w01 = wp[0];
            ulonglong2 w23 = wp[1];
#pragma unroll
            for (int j = 0; j < 4; j++) {
                ffma2(acc[0 * 4 + j], xv[j], w01.x);
                ffma2(acc[1 * 4 + j], xv[j], w01.y);
                ffma2(acc[2 * 4 + j], xv[j], w23.x);
                ffma2(acc[3 * 4 + j], xv[j], w23.y);
            }
        }
    }

    float sc[4], sh[4];
#pragma unroll
    for (int i = 0; i < 4; i++) {
        int d = ty * 4 + i;
        if (db == 0) {
            float inv = gq[d] * rsqrtf(vq[d] + 1e-5f);
            sc[i] = inv; sh[i] = bq[d] - mq[d] * inv;
        } else if (db == 1) {
            sc[i] = 1.f; sh[i] = 0.f;
        } else {
            int uvi = dcol0 + d;
            float inv = gv[uvi] * rsqrtf(vv[uvi] + 1e-5f);
            sc[i] = inv; sh[i] = bv[uvi] - mv[uvi] * inv;
        }
    }

    if (db < 2) {
        float* dst = (db == 0 ? g_q : g_k) + (size_t)b * 64 * NN;
#pragma unroll
        for (int i = 0; i < 4; i++) {
#pragma unroll
            for (int j = 0; j < 4; j++) {
                int n = n0 + ((tx + 16 * j) << 1);
                if (n < NN) {
                    float lo, hi; funpack(acc[i * 4 + j], lo, hi);
                    float* p = dst + (size_t)(ty * 4 + i) * NN + n;
                    p[0] = lo * sc[i] + sh[i];
                    p[1] = hi * sc[i] + sh[i];
                }
            }
        }
    } else {
        // v: n-major writes, 4 consecutive channels per thread -> float4
#pragma unroll
        for (int j = 0; j < 4; j++) {
            int n = n0 + ((tx + 16 * j) << 1);
            if (n < NN) {
                float4 a, c;
#pragma unroll
                for (int i = 0; i < 4; i++) {
                    float lo, hi; funpack(acc[i * 4 + j], lo, hi);
                    ((float*)&a)[i] = lo * sc[i] + sh[i];
                    ((float*)&c)[i] = hi * sc[i] + sh[i];
                }
                float* base = g_v2 + ((size_t)b * NN + n) * 256 + dcol0 + ty * 4;
                *(float4*)base         = a;
                *(float4*)(base + 256) = c;
            }
        }
    }
}

// ---------------- kernel 1: softmax stats only (max & 1/sum per row) ----------------
__global__ void __launch_bounds__(256) softmax_stats_kernel() {
    const int row = blockIdx.x;                 // b*64 + u*16 + k
    const float* base = g_k + (size_t)row * NN;
    const int t = threadIdx.x;
    __shared__ float red[8];

    float m = -3e38f;
    for (int i = t; i < NN; i += 256) m = fmaxf(m, base[i]);
#pragma unroll
    for (int o = 16; o; o >>= 1) m = fmaxf(m, __shfl_xor_sync(0xffffffffu, m, o));
    if ((t & 31) == 0) red[t >> 5] = m;
    __syncthreads();
    float mx = red[0];
#pragma unroll
    for (int w = 1; w < 8; w++) mx = fmaxf(mx, red[w]);
    __syncthreads();

    float s = 0.f;
    for (int i = t; i < NN; i += 256) s += expf(base[i] - mx);
#pragma unroll
    for (int o = 16; o; o >>= 1) s += __shfl_xor_sync(0xffffffffu, s, o);
    if ((t & 31) == 0) red[t >> 5] = s;
    __syncthreads();
    if (t == 0) {
        float S = 0.f;
#pragma unroll
        for (int w = 0; w < 8; w++) S += red[w];
        g_m[row]  = mx;
        g_is[row] = 1.f / S;
    }
}

// ---------------- kernel 2: Lc[b,k,v], softmax applied on the fly ----------------
// R16: ks stride 17 -> 20 so the 4 broadcast k reads per m are one aligned
// LDS.128 (float4) instead of 4 scalar LDS.32.
__global__ void __launch_bounds__(256) lc_kernel() {
    const int b  = blockIdx.x;
    const int sp = blockIdx.y;
    __shared__ float ks[56 * 20];
    __shared__ float vs[56 * 65];
    const int t  = threadIdx.x;
    const int vc = t & 63;
    const int kg = t >> 6;

    const int m0 = sp * 56;
    float acc[4] = {0.f, 0.f, 0.f, 0.f};
    for (int u = 0; u < 4; u++) {
        __syncthreads();
        for (int s = t; s < 16 * 56; s += 256) {
            int kc = s / 56, m = s % 56;
            int row = (b * 4 + u) * 16 + kc;
            float val = g_k[(size_t)row * NN + m0 + m];
            ks[m * 20 + kc] = expf(val - g_m[row]) * g_is[row];
        }
        // v tile from n-major g_v2: row m = 64 contiguous floats
        for (int s = t; s < 56 * 16; s += 256) {
            int m = s >> 4, c4 = s & 15;
            float4 v4 = *(const float4*)(g_v2
                + ((size_t)b * NN + m0 + m) * 256 + u * 64 + c4 * 4);
            float* d = &vs[m * 65 + c4 * 4];
            d[0] = v4.x; d[1] = v4.y; d[2] = v4.z; d[3] = v4.w;
        }
        __syncthreads();
        for (int m = 0; m < 56; m++) {
            float vvv = vs[m * 65 + vc];
            float4 kv = *(const float4*)&ks[m * 20 + kg * 4];
            acc[0] += kv.x * vvv;
            acc[1] += kv.y * vvv;
            acc[2] += kv.z * vvv;
            acc[3] += kv.w * vvv;
        }
    }
#pragma unroll
    for (int i = 0; i < 4; i++)
        atomicAdd(&g_Lc[((size_t)b * 16 + kg * 4 + i) * DVV + vc], acc[i]);
}

// ---------------- kernel 3 (launch idx 3 = ncu-captured): full lambda ----------
// Unchanged from R15 (fragile at 128 regs; current best 885 us).
// smem: qwd ull[2][3780] @0 (15120 f); wd ull[3840] @15120 (7680 f);
//       total 22800 f = 91200 B -> 2 CTA/SM.
#define LSM_WD    15120
#define LSM_TOTAL (22800 * 4)

__global__ void __launch_bounds__(256, 2) lambda_yp_kernel(
    const float* __restrict__ posw, const float* __restrict__ posb,
    float* __restrict__ out)
{
    extern __shared__ float sm[];
    ull* qwd = (ull*)sm;               // [2][3780]
    ull* wd  = (ull*)(sm + LSM_WD);    // [3840]

    const int y    = blockIdx.x;
    const int b    = blockIdx.y;
    const int t    = threadIdx.x;
    const int w    = t >> 5;
    const int lane = t & 31;
    // phase-1 role: warp -> (h, dx half)
    const int ph   = w >> 1;
    const int pd0  = (w & 1) ? 8 : 0;
    const int pdn  = (w & 1) ? 7 : 8;
    // phase-2 role: warp -> (x-slice, h-pair); lane -> (x-half, v-quad)
    const int wx   = w & 3;
    const int hh   = w >> 2;
    const int xh   = lane >> 4;
    const int vq   = lane & 15;
    const int xbase = 14 * wx + 7 * xh;

    // per-xi qwd offsets (ull units) incl. h-pair select
    int xo[7];
#pragma unroll
    for (int xi = 0; xi < 7; xi++) {
        int p = xbase + xi;
        xo[xi] = (p >> 2) * 18 + ((p >> 1) & 1) * 8 + (p & 1) * 4 + hh * 2;
    }

    ulonglong2 acc[2][7];
#pragma unroll
    for (int j = 0; j < 2; j++)
#pragma unroll
        for (int xi = 0; xi < 7; xi++) { acc[j][xi].x = 0ull; acc[j][xi].y = 0ull; }

    const int dylo = (y < 7) ? 7 - y : 0;
    const int dyhi = (y > 48) ? 62 - y : 14;
    int buf = 0;

    auto stage_wd = [&](int u) {
        for (int s = t; s < 3840; s += 256) {
            int dy = s >> 8, k = (s >> 4) & 15, dx = s & 15;
            float val = (dx < 15)
                ? posw[(size_t)k * 900 + u * 225 + dy * 15 + dx] : 0.f;
            wd[s] = pack2(val);
        }
    };
    auto phase1 = [&](ull* qb, int dy) {
        if (lane >= 28) return;
        ull a[8];
#pragma unroll
        for (int j = 0; j < 8; j++) a[j] = 0ull;
        const float* qg = g_q + (size_t)(b * 64 + ph * 16) * NN + y * 56 + 2 * lane;
        const ulonglong2* wp = (const ulonglong2*)wd + dy * 128 + (pd0 >> 1);
#pragma unroll
        for (int k = 0; k < 16; k++) {
            ull qk = *(const ull*)(qg + (size_t)k * NN);
            ulonglong2 W01 = wp[k * 8 + 0];
            ulonglong2 W23 = wp[k * 8 + 1];
            ulonglong2 W45 = wp[k * 8 + 2];
            ulonglong2 W67 = wp[k * 8 + 3];
            ffma2(a[0], qk, W01.x); ffma2(a[1], qk, W01.y);
            ffma2(a[2], qk, W23.x); ffma2(a[3], qk, W23.y);
            ffma2(a[4], qk, W45.x); ffma2(a[5], qk, W45.y);
            ffma2(a[6], qk, W67.x); ffma2(a[7], qk, W67.y);
        }
        const int gq_ = lane >> 1;
        const int pr  = lane & 1;
#pragma unroll
        for (int j = 0; j < 8; j++) {
            if (j < pdn) {
                float lo, hi; funpack(a[j], lo, hi);
                ull* dst = qb + (size_t)(((pd0 + j) * 14 + gq_) * 18 + pr * 8 + ph);
                dst[0] = fpack(lo, lo);   // x0 = 2*lane
                dst[4] = fpack(hi, hi);   // x1 = 2*lane+1
            }
        }
    };
    auto phase2 = [&](const ull* qb, int u, int row) {
        const float* vb = g_v2 + ((size_t)b * NN + (size_t)row * 56) * 256
                        + u * 64 + vq * 4;
        auto ldv = [&](int x) -> ulonglong2 {
            ulonglong2 v; v.x = 0ull; v.y = 0ull;
            if ((unsigned)x < 56u)
                v = *(const ulonglong2*)(vb + (size_t)x * 256);
            return v;
        };
        // window invariant at chunk c: vwin[i] = v[xbase + 3c - 7 + i]
        ulonglong2 vwin[9];
#pragma unroll
        for (int i = 0; i < 9; i++) vwin[i] = ldv(xbase - 7 + i);
#pragma unroll
        for (int c = 0; c < 5; c++) {
#pragma unroll
            for (int dxl = 0; dxl < 3; dxl++) {
                const ull* qbase = qb + (c * 3 + dxl) * 252;
#pragma unroll
                for (int xi = 0; xi < 7; xi++) {
                    ulonglong2 q01 = *(const ulonglong2*)(qbase + xo[xi]);
                    ulonglong2 a = vwin[xi + dxl];
                    ffma2(acc[0][xi].x, a.x, q01.x);
                    ffma2(acc[0][xi].y, a.y, q01.x);
                    ffma2(acc[1][xi].x, a.x, q01.y);
                    ffma2(acc[1][xi].y, a.y, q01.y);
                }
            }
            if (c < 4) {
#pragma unroll
                for (int i = 0; i < 6; i++) vwin[i] = vwin[i + 3];
                vwin[6] = ldv(xbase + 3 * c + 2);
                vwin[7] = ldv(xbase + 3 * c + 3);
                vwin[8] = ldv(xbase + 3 * c + 4);
            }
        }
    };

    for (int u = 0; u < 4; u++) {
        __syncthreads();                      // prior phase1/phase2 done -> wd, qwd free
        stage_wd(u);
        __syncthreads();                      // wd visible

        phase1(qwd + buf * 3780, dylo);

        for (int dy = dylo; dy <= dyhi; dy++) {
            __syncthreads();                  // qwd[buf] ready; qwd[buf^1] free
            if (dy < dyhi) phase1(qwd + (buf ^ 1) * 3780, dy + 1);
            phase2(qwd + buf * 3780, u, y + dy - 7);
            buf ^= 1;
        }
    }

    // ---- fused Yc: acc += q · (Lc + pos_b), via 16-tap phase-2 pass ----
    __syncthreads();                          // main loop done; qwd+wd free
    if (lane < 28) {
        const float* qg = g_q + (size_t)(b * 64 + ph * 16) * NN + y * 56 + 2 * lane;
        const int gq_ = lane >> 1;
        const int pr  = lane & 1;
        const int kb  = (w & 1) * 8;
#pragma unroll
        for (int kk = 0; kk < 8; kk++) {
            float lo, hi;
            funpack(*(const ull*)(qg + (size_t)(kb + kk) * NN), lo, hi);
            ull* dst = qwd + (size_t)((kb + kk) * 252 + gq_ * 18 + pr * 8 + ph);
            dst[0] = fpack(lo, lo);
            dst[4] = fpack(hi, hi);
        }
    }
    for (int s = t; s < 512; s += 256) {
        int k = s >> 5, vp = s & 31;
        float pb = posb[k];
        const float* lc2 = g_Lc + (size_t)b * 1024 + k * 64 + 2 * vp;
        wd[s] = fpack(lc2[0] + pb, lc2[1] + pb);
    }
    __syncthreads();
#pragma unroll
    for (int k = 0; k < 16; k++) {
        const ull* qbase = qwd + k * 252;
        ulonglong2 l2 = *(const ulonglong2*)(wd + k * 32 + vq * 2);
#pragma unroll
        for (int xi = 0; xi < 7; xi++) {
            ulonglong2 q01 = *(const ulonglong2*)(qbase + xo[xi]);
            ffma2(acc[0][xi].x, l2.x, q01.x);
            ffma2(acc[0][xi].y, l2.y, q01.x);
            ffma2(acc[1][xi].x, l2.x, q01.y);
            ffma2(acc[1][xi].y, l2.y, q01.y);
        }
    }

    // ---- epilogue: 2 rounds; hh=0 warps stage h=r, hh=1 stage h=2+r ----
    __syncthreads();                          // yc pass done; wd free for ybuf
    float* ybufA = (float*)wd;                // [64][57]
    float* ybufB = ybufA + 64 * 57;
#pragma unroll
    for (int r = 0; r < 2; r++) {
        float* yb = hh ? ybufB : ybufA;
#pragma unroll
        for (int xi = 0; xi < 7; xi++) {
            int x = xbase + xi;
            float v0, v1, v2, v3;
            funpack(acc[r][xi].x, v0, v1);
            funpack(acc[r][xi].y, v2, v3);
            yb[(4 * vq + 0) * 57 + x] = v0;
            yb[(4 * vq + 1) * 57 + x] = v1;
            yb[(4 * vq + 2) * 57 + x] = v2;
            yb[(4 * vq + 3) * 57 + x] = v3;
        }
        __syncthreads();
        float* oA = out + ((size_t)(b * 256 + r * 64)) * NN + y * 56;
        float* oB = out + ((size_t)(b * 256 + (2 + r) * 64)) * NN + y * 56;
        for (int s = t; s < 64 * 14; s += 256) {
            int v = s / 14, x4 = s % 14;
            const float* sa = ybufA + v * 57 + x4 * 4;
            float4 f; f.x = sa[0]; f.y = sa[1]; f.z = sa[2]; f.w = sa[3];
            *(float4*)(oA + (size_t)v * NN + x4 * 4) = f;
            const float* sb = ybufB + v * 57 + x4 * 4;
            float4 g2; g2.x = sb[0]; g2.y = sb[1]; g2.z = sb[2]; g2.w = sb[3];
            *(float4*)(oB + (size_t)v * NN + x4 * 4) = g2;
        }
        __syncthreads();
    }
}

// ---------------- launch (4 kernels; lambda at index 3 => ncu captures it) --------
extern "C" void kernel_launch(void* const* d_in, const int* in_sizes, int n_in,
                              void* d_out, int out_size) {
    const float* x    = (const float*)d_in[0];
    const float* Wq   = (const float*)d_in[1];
    const float* Wk   = (const float*)d_in[2];
    const float* Wv   = (const float*)d_in[3];
    const float* posw = (const float*)d_in[4];
    const float* posb = (const float*)d_in[5];
    const float* gq   = (const float*)d_in[6];
    const float* bq   = (const float*)d_in[7];
    const float* mq   = (const float*)d_in[8];
    const float* vq   = (const float*)d_in[9];
    const float* gv   = (const float*)d_in[10];
    const float* bv   = (const float*)d_in[11];
    const float* mv   = (const float*)d_in[12];
    const float* vv   = (const float*)d_in[13];
    float* out = (float*)d_out;

    cudaFuncSetAttribute(lambda_yp_kernel,
                         cudaFuncAttributeMaxDynamicSharedMemorySize, LSM_TOTAL);

    proj_kernel<<<dim3(25, 6, 16), 256>>>(x, Wq, Wk, Wv,
                                          gq, bq, mq, vq,
                                          gv, bv, mv, vv);            // idx 0 (zeroes Lc)
    softmax_stats_kernel<<<BB * 64, 256>>>();                         // idx 1
    lc_kernel<<<dim3(16, 56), 256>>>();                               // idx 2
    lambda_yp_kernel<<<dim3(56, 16), 256, LSM_TOTAL>>>(posw, posb, out); // idx 3 <- ncu
}

// round 17
// speedup vs baseline: 1.0400x; 1.0400x over previous
#include <cuda_runtime.h>
#include <cuda_bf16.h>

// ---------------- problem constants ----------------
#define BB     16
#define CCH    256
#define HH     56
#define WWID   56
#define NN     3136          // 56*56
#define NHEADS 4
#define DK     16
#define DU     4
#define DVV    64
#define RR     15
// conv pad = 7

typedef unsigned long long ull;

// ---------------- scratch (device globals; no allocations allowed) ----------------
__device__ float g_q[BB * 64 * NN];    // [b][h*16+k][n]   (BN applied)
__device__ float g_k[BB * 64 * NN];    // [b][u*16+k][n]   (raw logits; softmax fused into lc)
__device__ float g_v2[BB * NN * 256];  // [b][n][u*64+v]   (n-major, BN applied)
__device__ float g_Lc[BB * DK * DVV];  // [b][k][v]
__device__ float g_m[BB * 64];         // per-row softmax max
__device__ float g_is[BB * 64];        // per-row 1/sum

// ---------------- f32x2 helpers (sm_103a packed fp32 pipe) ----------------
__device__ __forceinline__ void ffma2(ull &d, ull a, ull b) {
    asm volatile("fma.rn.f32x2 %0, %1, %2, %0;" : "+l"(d) : "l"(a), "l"(b));
}
__device__ __forceinline__ ull pack2(float x) {
    ull r; asm("mov.b64 %0, {%1, %1};" : "=l"(r) : "f"(x)); return r;
}
__device__ __forceinline__ ull fpack(float lo, float hi) {
    ull r; asm("mov.b64 %0, {%1, %2};" : "=l"(r) : "f"(lo), "f"(hi)); return r;
}
__device__ __forceinline__ void funpack(ull v, float &lo, float &hi) {
    asm("mov.b64 {%0, %1}, %2;" : "=f"(lo), "=f"(hi) : "l"(v));
}

// ---------------- kernel 0: projections + BN; v written n-major; zeroes Lc ------
// R17: staging vectorized (float4 xs / Ws loads+stores, exact-guard since
// NN%4==0 and all bases 16B-aligned); q/k epilogue pair-stores as STG.64.
// Inner loop identical to R15 (R16's Wsd experiment regressed; reverted).
__global__ void __launch_bounds__(256) proj_kernel(
    const float* __restrict__ x,
    const float* __restrict__ Wq, const float* __restrict__ Wk, const float* __restrict__ Wv,
    const float* __restrict__ gq, const float* __restrict__ bq,
    const float* __restrict__ mq, const float* __restrict__ vq,
    const float* __restrict__ gv, const float* __restrict__ bv,
    const float* __restrict__ mv, const float* __restrict__ vv)
{
    __shared__ float xs[32 * 128];
    __shared__ float Ws[32 * 64];

    const int b  = blockIdx.z;
    const int db = blockIdx.y;
    const int n0 = blockIdx.x * 128;
    const int t  = threadIdx.x;
    const int tx = t & 15;
    const int ty = t >> 4;

    // fold zero_lc in (g_Lc only written later by lc_kernel)
    if (db == 0 && blockIdx.x == 0)
        for (int s = t; s < 1024; s += 256) g_Lc[(size_t)b * 1024 + s] = 0.f;

    const float* Wsrc; int dstride, dcol0;
    if (db == 0)      { Wsrc = Wq; dstride = 64;  dcol0 = 0; }
    else if (db == 1) { Wsrc = Wk; dstride = 64;  dcol0 = 0; }
    else              { Wsrc = Wv; dstride = 256; dcol0 = (db - 2) * 64; }

    ull acc[16];
#pragma unroll
    for (int i = 0; i < 16; i++) acc[i] = 0ull;

    for (int c0 = 0; c0 < CCH; c0 += 32) {
        __syncthreads();
        // xs staging: float4 (32 rows x 128 cols = 1024 float4)
        for (int s = t; s < 1024; s += 256) {
            int cc = s >> 5, n4 = s & 31;          // n4: float4 index in row
            int g = n0 + n4 * 4;
            float4 v4 = make_float4(0.f, 0.f, 0.f, 0.f);
            if (g < NN)                             // exact: g%4==0, NN%4==0
                v4 = *(const float4*)(x + (size_t)(b * CCH + c0 + cc) * NN + g);
            *(float4*)&xs[cc * 128 + n4 * 4] = v4;
        }
        // Ws staging: float4 (32 rows x 64 cols = 512 float4)
        for (int s = t; s < 512; s += 256) {
            int cc = s >> 4, d4 = s & 15;
            float4 w4 = *(const float4*)(Wsrc
                + (size_t)(c0 + cc) * dstride + dcol0 + d4 * 4);
            *(float4*)&Ws[cc * 64 + d4 * 4] = w4;
        }
        __syncthreads();

#pragma unroll 8
        for (int ccl = 0; ccl < 32; ccl++) {
            ull xv[4];
#pragma unroll
            for (int j = 0; j < 4; j++)
                xv[j] = *(const ull*)&xs[ccl * 128 + ((tx + 16 * j) << 1)];
#pragma unroll
            for (int i = 0; i < 4; i++) {
                ull w2 = pack2(Ws[ccl * 64 + ty * 4 + i]);
#pragma unroll
                for (int j = 0; j < 4; j++) ffma2(acc[i * 4 + j], xv[j], w2);
            }
        }
    }

    float sc[4], sh[4];
#pragma unroll
    for (int i = 0; i < 4; i++) {
        int d = ty * 4 + i;
        if (db == 0) {
            float inv = gq[d] * rsqrtf(vq[d] + 1e-5f);
            sc[i] = inv; sh[i] = bq[d] - mq[d] * inv;
        } else if (db == 1) {
            sc[i] = 1.f; sh[i] = 0.f;
        } else {
            int uvi = dcol0 + d;
            float inv = gv[uvi] * rsqrtf(vv[uvi] + 1e-5f);
            sc[i] = inv; sh[i] = bv[uvi] - mv[uvi] * inv;
        }
    }

    if (db < 2) {
        float* dst = (db == 0 ? g_q : g_k) + (size_t)b * 64 * NN;
#pragma unroll
        for (int i = 0; i < 4; i++) {
#pragma unroll
            for (int j = 0; j < 4; j++) {
                int n = n0 + ((tx + 16 * j) << 1);
                if (n < NN) {
                    float lo, hi; funpack(acc[i * 4 + j], lo, hi);
                    // pair store as one STG.64 (8B-aligned: n even, NN even)
                    *(ull*)(dst + (size_t)(ty * 4 + i) * NN + n)
                        = fpack(lo * sc[i] + sh[i], hi * sc[i] + sh[i]);
                }
            }
        }
    } else {
        // v: n-major writes, 4 consecutive channels per thread -> float4
#pragma unroll
        for (int j = 0; j < 4; j++) {
            int n = n0 + ((tx + 16 * j) << 1);
            if (n < NN) {
                float4 a, c;
#pragma unroll
                for (int i = 0; i < 4; i++) {
                    float lo, hi; funpack(acc[i * 4 + j], lo, hi);
                    ((float*)&a)[i] = lo * sc[i] + sh[i];
                    ((float*)&c)[i] = hi * sc[i] + sh[i];
                }
                float* base = g_v2 + ((size_t)b * NN + n) * 256 + dcol0 + ty * 4;
                *(float4*)base         = a;
                *(float4*)(base + 256) = c;
            }
        }
    }
}

// ---------------- kernel 1: softmax stats only (max & 1/sum per row) ----------------
__global__ void __launch_bounds__(256) softmax_stats_kernel() {
    const int row = blockIdx.x;                 // b*64 + u*16 + k
    const float* base = g_k + (size_t)row * NN;
    const int t = threadIdx.x;
    __shared__ float red[8];

    float m = -3e38f;
    for (int i = t; i < NN; i += 256) m = fmaxf(m, base[i]);
#pragma unroll
    for (int o = 16; o; o >>= 1) m = fmaxf(m, __shfl_xor_sync(0xffffffffu, m, o));
    if ((t & 31) == 0) red[t >> 5] = m;
    __syncthreads();
    float mx = red[0];
#pragma unroll
    for (int w = 1; w < 8; w++) mx = fmaxf(mx, red[w]);
    __syncthreads();

    float s = 0.f;
    for (int i = t; i < NN; i += 256) s += expf(base[i] - mx);
#pragma unroll
    for (int o = 16; o; o >>= 1) s += __shfl_xor_sync(0xffffffffu, s, o);
    if ((t & 31) == 0) red[t >> 5] = s;
    __syncthreads();
    if (t == 0) {
        float S = 0.f;
#pragma unroll
        for (int w = 0; w < 8; w++) S += red[w];
        g_m[row]  = mx;
        g_is[row] = 1.f / S;
    }
}

// ---------------- kernel 2: Lc[b,k,v], softmax applied on the fly ----------------
// R15 version exactly (R16's stride-20 change caused 4-way STS conflicts).
__global__ void __launch_bounds__(256) lc_kernel() {
    const int b  = blockIdx.x;
    const int sp = blockIdx.y;
    __shared__ float ks[56 * 17];
    __shared__ float vs[56 * 65];
    const int t  = threadIdx.x;
    const int vc = t & 63;
    const int kg = t >> 6;

    const int m0 = sp * 56;
    float acc[4] = {0.f, 0.f, 0.f, 0.f};
    for (int u = 0; u < 4; u++) {
        __syncthreads();
        for (int s = t; s < 16 * 56; s += 256) {
            int kc = s / 56, m = s % 56;
            int row = (b * 4 + u) * 16 + kc;
            float val = g_k[(size_t)row * NN + m0 + m];
            ks[m * 17 + kc] = expf(val - g_m[row]) * g_is[row];
        }
        // v tile from n-major g_v2: row m = 64 contiguous floats
        for (int s = t; s < 56 * 16; s += 256) {
            int m = s >> 4, c4 = s & 15;
            float4 v4 = *(const float4*)(g_v2
                + ((size_t)b * NN + m0 + m) * 256 + u * 64 + c4 * 4);
            float* d = &vs[m * 65 + c4 * 4];
            d[0] = v4.x; d[1] = v4.y; d[2] = v4.z; d[3] = v4.w;
        }
        __syncthreads();
        for (int m = 0; m < 56; m++) {
            float vvv = vs[m * 65 + vc];
#pragma unroll
            for (int i = 0; i < 4; i++) acc[i] += ks[m * 17 + kg * 4 + i] * vvv;
        }
    }
#pragma unroll
    for (int i = 0; i < 4; i++)
        atomicAdd(&g_Lc[((size_t)b * 16 + kg * 4 + i) * DVV + vc], acc[i]);
}

// ---------------- kernel 3 (launch idx 3 = ncu-captured): full lambda ----------
// Unchanged from R15 (fragile at 128 regs; stable 885 us).
// smem: qwd ull[2][3780] @0 (15120 f); wd ull[3840] @15120 (7680 f);
//       total 22800 f = 91200 B -> 2 CTA/SM.
#define LSM_WD    15120
#define LSM_TOTAL (22800 * 4)

__global__ void __launch_bounds__(256, 2) lambda_yp_kernel(
    const float* __restrict__ posw, const float* __restrict__ posb,
    float* __restrict__ out)
{
    extern __shared__ float sm[];
    ull* qwd = (ull*)sm;               // [2][3780]
    ull* wd  = (ull*)(sm + LSM_WD);    // [3840]

    const int y    = blockIdx.x;
    const int b    = blockIdx.y;
    const int t    = threadIdx.x;
    const int w    = t >> 5;
    const int lane = t & 31;
    // phase-1 role: warp -> (h, dx half)
    const int ph   = w >> 1;
    const int pd0  = (w & 1) ? 8 : 0;
    const int pdn  = (w & 1) ? 7 : 8;
    // phase-2 role: warp -> (x-slice, h-pair); lane -> (x-half, v-quad)
    const int wx   = w & 3;
    const int hh   = w >> 2;
    const int xh   = lane >> 4;
    const int vq   = lane & 15;
    const int xbase = 14 * wx + 7 * xh;

    // per-xi qwd offsets (ull units) incl. h-pair select
    int xo[7];
#pragma unroll
    for (int xi = 0; xi < 7; xi++) {
        int p = xbase + xi;
        xo[xi] = (p >> 2) * 18 + ((p >> 1) & 1) * 8 + (p & 1) * 4 + hh * 2;
    }

    ulonglong2 acc[2][7];
#pragma unroll
    for (int j = 0; j < 2; j++)
#pragma unroll
        for (int xi = 0; xi < 7; xi++) { acc[j][xi].x = 0ull; acc[j][xi].y = 0ull; }

    const int dylo = (y < 7) ? 7 - y : 0;
    const int dyhi = (y > 48) ? 62 - y : 14;
    int buf = 0;

    auto stage_wd = [&](int u) {
        for (int s = t; s < 3840; s += 256) {
            int dy = s >> 8, k = (s >> 4) & 15, dx = s & 15;
            float val = (dx < 15)
                ? posw[(size_t)k * 900 + u * 225 + dy * 15 + dx] : 0.f;
            wd[s] = pack2(val);
        }
    };
    auto phase1 = [&](ull* qb, int dy) {
        if (lane >= 28) return;
        ull a[8];
#pragma unroll
        for (int j = 0; j < 8; j++) a[j] = 0ull;
        const float* qg = g_q + (size_t)(b * 64 + ph * 16) * NN + y * 56 + 2 * lane;
        const ulonglong2* wp = (const ulonglong2*)wd + dy * 128 + (pd0 >> 1);
#pragma unroll
        for (int k = 0; k < 16; k++) {
            ull qk = *(const ull*)(qg + (size_t)k * NN);
            ulonglong2 W01 = wp[k * 8 + 0];
            ulonglong2 W23 = wp[k * 8 + 1];
            ulonglong2 W45 = wp[k * 8 + 2];
            ulonglong2 W67 = wp[k * 8 + 3];
            ffma2(a[0], qk, W01.x); ffma2(a[1], qk, W01.y);
            ffma2(a[2], qk, W23.x); ffma2(a[3], qk, W23.y);
            ffma2(a[4], qk, W45.x); ffma2(a[5], qk, W45.y);
            ffma2(a[6], qk, W67.x); ffma2(a[7], qk, W67.y);
        }
        const int gq_ = lane >> 1;
        const int pr  = lane & 1;
#pragma unroll
        for (int j = 0; j < 8; j++) {
            if (j < pdn) {
                float lo, hi; funpack(a[j], lo, hi);
                ull* dst = qb + (size_t)(((pd0 + j) * 14 + gq_) * 18 + pr * 8 + ph);
                dst[0] = fpack(lo, lo);   // x0 = 2*lane
                dst[4] = fpack(hi, hi);   // x1 = 2*lane+1
            }
        }
    };
    auto phase2 = [&](const ull* qb, int u, int row) {
        const float* vb = g_v2 + ((size_t)b * NN + (size_t)row * 56) * 256
                        + u * 64 + vq * 4;
        auto ldv = [&](int x) -> ulonglong2 {
            ulonglong2 v; v.x = 0ull; v.y = 0ull;
            if ((unsigned)x < 56u)
                v = *(const ulonglong2*)(vb + (size_t)x * 256);
            return v;
        };
        // window invariant at chunk c: vwin[i] = v[xbase + 3c - 7 + i]
        ulonglong2 vwin[9];
#pragma unroll
        for (int i = 0; i < 9; i++) vwin[i] = ldv(xbase - 7 + i);
#pragma unroll
        for (int c = 0; c < 5; c++) {
#pragma unroll
            for (int dxl = 0; dxl < 3; dxl++) {
                const ull* qbase = qb + (c * 3 + dxl) * 252;
#pragma unroll
                for (int xi = 0; xi < 7; xi++) {
                    ulonglong2 q01 = *(const ulonglong2*)(qbase + xo[xi]);
                    ulonglong2 a = vwin[xi + dxl];
                    ffma2(acc[0][xi].x, a.x, q01.x);
                    ffma2(acc[0][xi].y, a.y, q01.x);
                    ffma2(acc[1][xi].x, a.x, q01.y);
                    ffma2(acc[1][xi].y, a.y, q01.y);
                }
            }
            if (c < 4) {
#pragma unroll
                for (int i = 0; i < 6; i++) vwin[i] = vwin[i + 3];
                vwin[6] = ldv(xbase + 3 * c + 2);
                vwin[7] = ldv(xbase + 3 * c + 3);
                vwin[8] = ldv(xbase + 3 * c + 4);
            }
        }
    };

    for (int u = 0; u < 4; u++) {
        __syncthreads();                      // prior phase1/phase2 done -> wd, qwd free
        stage_wd(u);
        __syncthreads();                      // wd visible

        phase1(qwd + buf * 3780, dylo);

        for (int dy = dylo; dy <= dyhi; dy++) {
            __syncthreads();                  // qwd[buf] ready; qwd[buf^1] free
            if (dy < dyhi) phase1(qwd + (buf ^ 1) * 3780, dy + 1);
            phase2(qwd + buf * 3780, u, y + dy - 7);
            buf ^= 1;
        }
    }

    // ---- fused Yc: acc += q · (Lc + pos_b), via 16-tap phase-2 pass ----
    __syncthreads();                          // main loop done; qwd+wd free
    if (lane < 28) {
        const float* qg = g_q + (size_t)(b * 64 + ph * 16) * NN + y * 56 + 2 * lane;
        const int gq_ = lane >> 1;
        const int pr  = lane & 1;
        const int kb  = (w & 1) * 8;
#pragma unroll
        for (int kk = 0; kk < 8; kk++) {
            float lo, hi;
            funpack(*(const ull*)(qg + (size_t)(kb + kk) * NN), lo, hi);
            ull* dst = qwd + (size_t)((kb + kk) * 252 + gq_ * 18 + pr * 8 + ph);
            dst[0] = fpack(lo, lo);
            dst[4] = fpack(hi, hi);
        }
    }
    for (int s = t; s < 512; s += 256) {
        int k = s >> 5, vp = s & 31;
        float pb = posb[k];
        const float* lc2 = g_Lc + (size_t)b * 1024 + k * 64 + 2 * vp;
        wd[s] = fpack(lc2[0] + pb, lc2[1] + pb);
    }
    __syncthreads();
#pragma unroll
    for (int k = 0; k < 16; k++) {
        const ull* qbase = qwd + k * 252;
        ulonglong2 l2 = *(const ulonglong2*)(wd + k * 32 + vq * 2);
#pragma unroll
        for (int xi = 0; xi < 7; xi++) {
            ulonglong2 q01 = *(const ulonglong2*)(qbase + xo[xi]);
            ffma2(acc[0][xi].x, l2.x, q01.x);
            ffma2(acc[0][xi].y, l2.y, q01.x);
            ffma2(acc[1][xi].x, l2.x, q01.y);
            ffma2(acc[1][xi].y, l2.y, q01.y);
        }
    }

    // ---- epilogue: 2 rounds; hh=0 warps stage h=r, hh=1 stage h=2+r ----
    __syncthreads();                          // yc pass done; wd free for ybuf
    float* ybufA = (float*)wd;                // [64][57]
    float* ybufB = ybufA + 64 * 57;
#pragma unroll
    for (int r = 0; r < 2; r++) {
        float* yb = hh ? ybufB : ybufA;
#pragma unroll
        for (int xi = 0; xi < 7; xi++) {
            int x = xbase + xi;
            float v0, v1, v2, v3;
            funpack(acc[r][xi].x, v0, v1);
            funpack(acc[r][xi].y, v2, v3);
            yb[(4 * vq + 0) * 57 + x] = v0;
            yb[(4 * vq + 1) * 57 + x] = v1;
            yb[(4 * vq + 2) * 57 + x] = v2;
            yb[(4 * vq + 3) * 57 + x] = v3;
        }
        __syncthreads();
        float* oA = out + ((size_t)(b * 256 + r * 64)) * NN + y * 56;
        float* oB = out + ((size_t)(b * 256 + (2 + r) * 64)) * NN + y * 56;
        for (int s = t; s < 64 * 14; s += 256) {
            int v = s / 14, x4 = s % 14;
            const float* sa = ybufA + v * 57 + x4 * 4;
            float4 f; f.x = sa[0]; f.y = sa[1]; f.z = sa[2]; f.w = sa[3];
            *(float4*)(oA + (size_t)v * NN + x4 * 4) = f;
            const float* sb = ybufB + v * 57 + x4 * 4;
            float4 g2; g2.x = sb[0]; g2.y = sb[1]; g2.z = sb[2]; g2.w = sb[3];
            *(float4*)(oB + (size_t)v * NN + x4 * 4) = g2;
        }
        __syncthreads();
    }
}

// ---------------- launch (4 kernels; lambda at index 3 => ncu captures it) --------
extern "C" void kernel_launch(void* const* d_in, const int* in_sizes, int n_in,
                              void* d_out, int out_size) {
    const float* x    = (const float*)d_in[0];
    const float* Wq   = (const float*)d_in[1];
    const float* Wk   = (const float*)d_in[2];
    const float* Wv   = (const float*)d_in[3];
    const float* posw = (const float*)d_in[4];
    const float* posb = (const float*)d_in[5];
    const float* gq   = (const float*)d_in[6];
    const float* bq   = (const float*)d_in[7];
    const float* mq   = (const float*)d_in[8];
    const float* vq   = (const float*)d_in[9];
    const float* gv   = (const float*)d_in[10];
    const float* bv   = (const float*)d_in[11];
    const float* mv   = (const float*)d_in[12];
    const float* vv   = (const float*)d_in[13];
    float* out = (float*)d_out;

    cudaFuncSetAttribute(lambda_yp_kernel,
                         cudaFuncAttributeMaxDynamicSharedMemorySize, LSM_TOTAL);

    proj_kernel<<<dim3(25, 6, 16), 256>>>(x, Wq, Wk, Wv,
                                          gq, bq, mq, vq,
                                          gv, bv, mv, vv);            // idx 0 (zeroes Lc)
    softmax_stats_kernel<<<BB * 64, 256>>>();                         // idx 1
    lc_kernel<<<dim3(16, 56), 256>>>();                               // idx 2
    lambda_yp_kernel<<<dim3(56, 16), 256, LSM_TOTAL>>>(posw, posb, out); // idx 3 <- ncu
}